// round 9
// baseline (speedup 1.0000x reference)
#include <cuda_runtime.h>
#include <cstdint>

#define BATCH 512
#define TSEQ  64
#define P_DIM 8
#define Q_DIM 24
#define N_DIM 32
#define PQ    (P_DIM * Q_DIM)   // 192
#define SXP   28                // padded row stride for sx  (8 x 28)
#define SXTP  12                // padded row stride for sxT (24 x 12)
#define CCP   40                // padded column stride for 4-column half-panels
#define CPAD  36                // dist: padded row stride for 32x32 yb
#define RPAD  12                // dist: padded row stride for 32x8 panels

// Scratch (no cudaMalloc allowed)
__device__ float g_U[2 * BATCH * N_DIM * P_DIM];  // 1024 x (32x8) row-major panels

// ---------------------------------------------------------------------------
// seq_kernel: 2048 blocks x 64 threads. Block = (panel, half): half-panel of
// 4 columns. Columns of C evolve independently under C' = Y C, so the split
// is exact. Quadratic Cayley (error 2||X||^3 ~ 1e-6/step):
//   G = X C ;  C' = C - 2G + 2XG,  X = [[0,x],[-x^T,0]], x 8x24.
//
// Threads: tid<32 "top": owns (r=tid>>2, c=tid&3), 24 FMA/phase.
//          tid>=32 "bottom": owns rows 8+3*jg+{0,1,2} (jg=(tid-32)>>2), col c.
// x in shared in both layouts (row-major sx, transposed sxT), double-buffered;
// commit mappings chosen so all STS/LDS in the loop are bank-conflict-free.
// ---------------------------------------------------------------------------
__global__ __launch_bounds__(64, 14) void seq_kernel(
    const int*   __restrict__ s1,
    const int*   __restrict__ s2,
    const float* __restrict__ emb_q,
    const float* __restrict__ emb_a,
    const float* __restrict__ transforms)
{
    const int panel = blockIdx.x >> 1;
    const int half  = blockIdx.x & 1;
    const bool is_q = (panel < BATCH);
    const int  b    = is_q ? panel : (panel - BATCH);
    const int  tid  = threadIdx.x;
    const bool top  = (tid < 32);

    const float* emb  = is_q ? emb_q : emb_a;
    const int*   sent = is_q ? s1    : s2;

    __shared__ __align__(16) float sx [2][8 * SXP];    // row-major padded
    __shared__ __align__(16) float sxT[2][24 * SXTP];  // transposed padded
    __shared__ __align__(16) float sC[4 * CCP];
    __shared__ __align__(16) float sG[4 * CCP];
    __shared__ int stok[TSEQ];

    // compute geometry
    const int c  = tid & 3;
    const int r  = tid >> 2;            // top only (0..7)
    const int jg = (tid - 32) >> 2;     // bottom only (0..7)
    const int j0 = 3 * jg;

    // x-commit geometry (bank-conflict-free bijections)
    const int w  = tid >> 5;            // warp 0/1
    const int iS = tid & 7;
    int eS[3], aS[3], eT[3], aT[3];
    float tfS[3], tfT[3];
    #pragma unroll
    for (int m = 0; m < 3; ++m) {
        int kS = ((tid >> 3) & 3) + 4 * (2 * m + w);        // 0..23
        int jT = 6 * ((tid >> 3) & 3) + 2 * m + w;          // 0..23
        eS[m] = iS * Q_DIM + kS;   aS[m] = SXP  * iS + kS;
        eT[m] = iS * Q_DIM + jT;   aT[m] = SXTP * jT + iS;
        tfS[m] = is_q ? transforms[eS[m]] : 1.0f;
        tfT[m] = is_q ? transforms[eT[m]] : 1.0f;
    }

    stok[tid] = sent[b * TSEQ + tid];

    // registers: own panel entries (top uses cown0 only)
    float cown0 = 0.f, cown1 = 0.f, cown2 = 0.f;
    if (top) cown0 = (r == half * 4 + c) ? 1.0f : 0.0f;

    // init shared C
    if (top) {
        sC[c * CCP + r] = cown0;
    } else {
        sC[c * CCP + 8 + j0 + 0] = 0.0f;
        sC[c * CCP + 8 + j0 + 1] = 0.0f;
        sC[c * CCP + 8 + j0 + 2] = 0.0f;
    }
    __syncthreads();

    // first x (t = 63) into buffer 1
    {
        size_t base = (size_t)stok[TSEQ - 1] * PQ;
        #pragma unroll
        for (int m = 0; m < 3; ++m) {
            sx [1][aS[m]] = emb[base + eS[m]] * tfS[m];
            sxT[1][aT[m]] = emb[base + eT[m]] * tfT[m];
        }
    }
    __syncthreads();

    float rx[24];

#define SEQ_STEP(BUF, T)                                                        \
    do {                                                                        \
        float vn0=0.f,vn1=0.f,vn2=0.f,wn0=0.f,wn1=0.f,wn2=0.f;                  \
        if ((T) > 0) {                                                          \
            size_t base = (size_t)stok[(T) - 1] * PQ;                           \
            vn0 = emb[base + eS[0]]; wn0 = emb[base + eT[0]];                   \
            vn1 = emb[base + eS[1]]; wn1 = emb[base + eT[1]];                   \
            vn2 = emb[base + eS[2]]; wn2 = emb[base + eT[2]];                   \
        }                                                                       \
        if (top) {                                                              \
            const float4* px = (const float4*)(sx[BUF] + r * SXP);              \
            _Pragma("unroll")                                                   \
            for (int m = 0; m < 6; ++m) {                                       \
                float4 v = px[m];                                               \
                rx[4*m]=v.x; rx[4*m+1]=v.y; rx[4*m+2]=v.z; rx[4*m+3]=v.w;       \
            }                                                                   \
        } else {                                                                \
            _Pragma("unroll")                                                   \
            for (int d = 0; d < 3; ++d) {                                       \
                const float4* pxt = (const float4*)(sxT[BUF] + (j0 + d) * SXTP);\
                float4 v0 = pxt[0], v1 = pxt[1];                                \
                rx[d*8+0]=v0.x; rx[d*8+1]=v0.y; rx[d*8+2]=v0.z; rx[d*8+3]=v0.w; \
                rx[d*8+4]=v1.x; rx[d*8+5]=v1.y; rx[d*8+6]=v1.z; rx[d*8+7]=v1.w; \
            }                                                                   \
        }                                                                       \
        float gown0, gown1 = 0.f, gown2 = 0.f;                                  \
        if (top) {                                                              \
            const float4* pc = (const float4*)(&sC[c * CCP + 8]);               \
            float a0=0.f,a1=0.f,a2=0.f,a3=0.f;                                  \
            _Pragma("unroll")                                                   \
            for (int m = 0; m < 6; ++m) {                                       \
                float4 v = pc[m];                                               \
                a0 += rx[4*m]*v.x;  a1 += rx[4*m+1]*v.y;                        \
                a2 += rx[4*m+2]*v.z; a3 += rx[4*m+3]*v.w;                       \
            }                                                                   \
            gown0 = (a0 + a1) + (a2 + a3);                                      \
            sG[c * CCP + r] = gown0;                                            \
        } else {                                                                \
            const float4* pc = (const float4*)(&sC[c * CCP]);                   \
            float4 v0 = pc[0], v1 = pc[1];                                      \
            _Pragma("unroll")                                                   \
            for (int d = 0; d < 3; ++d) {                                       \
                float g = rx[d*8+0]*v0.x + rx[d*8+1]*v0.y + rx[d*8+2]*v0.z      \
                        + rx[d*8+3]*v0.w + rx[d*8+4]*v1.x + rx[d*8+5]*v1.y      \
                        + rx[d*8+6]*v1.z + rx[d*8+7]*v1.w;                      \
                g = -g;                                                         \
                if (d == 0) gown0 = g; else if (d == 1) gown1 = g; else gown2 = g;\
                sG[c * CCP + 8 + j0 + d] = g;                                   \
            }                                                                   \
        }                                                                       \
        __syncthreads();                                                        \
        if (top) {                                                              \
            const float4* pg = (const float4*)(&sG[c * CCP + 8]);               \
            float a0=0.f,a1=0.f,a2=0.f,a3=0.f;                                  \
            _Pragma("unroll")                                                   \
            for (int m = 0; m < 6; ++m) {                                       \
                float4 v = pg[m];                                               \
                a0 += rx[4*m]*v.x;  a1 += rx[4*m+1]*v.y;                        \
                a2 += rx[4*m+2]*v.z; a3 += rx[4*m+3]*v.w;                       \
            }                                                                   \
            float h = (a0 + a1) + (a2 + a3);                                    \
            cown0 += 2.0f * (h - gown0);                                        \
            sC[c * CCP + r] = cown0;                                            \
        } else {                                                                \
            const float4* pg = (const float4*)(&sG[c * CCP]);                   \
            float4 v0 = pg[0], v1 = pg[1];                                      \
            _Pragma("unroll")                                                   \
            for (int d = 0; d < 3; ++d) {                                       \
                float h = rx[d*8+0]*v0.x + rx[d*8+1]*v0.y + rx[d*8+2]*v0.z      \
                        + rx[d*8+3]*v0.w + rx[d*8+4]*v1.x + rx[d*8+5]*v1.y      \
                        + rx[d*8+6]*v1.z + rx[d*8+7]*v1.w;                      \
                h = -h;                                                         \
                float go = (d == 0) ? gown0 : ((d == 1) ? gown1 : gown2);       \
                float cn = ((d == 0) ? cown0 : ((d == 1) ? cown1 : cown2))      \
                           + 2.0f * (h - go);                                   \
                if (d == 0) cown0 = cn; else if (d == 1) cown1 = cn; else cown2 = cn;\
                sC[c * CCP + 8 + j0 + d] = cn;                                  \
            }                                                                   \
        }                                                                       \
        if ((T) > 0) {                                                          \
            sx [(BUF)^1][aS[0]] = vn0 * tfS[0];                                 \
            sx [(BUF)^1][aS[1]] = vn1 * tfS[1];                                 \
            sx [(BUF)^1][aS[2]] = vn2 * tfS[2];                                 \
            sxT[(BUF)^1][aT[0]] = wn0 * tfT[0];                                 \
            sxT[(BUF)^1][aT[1]] = wn1 * tfT[1];                                 \
            sxT[(BUF)^1][aT[2]] = wn2 * tfT[2];                                 \
        }                                                                       \
        __syncthreads();                                                        \
    } while (0)

    for (int t2 = 31; t2 >= 0; --t2) {
        SEQ_STEP(1, 2 * t2 + 1);
        SEQ_STEP(0, 2 * t2);
    }
#undef SEQ_STEP

    // write final half-panel row-major to global: cols [half*4, half*4+4)
    #pragma unroll
    for (int k = 0; k < 2; ++k) {
        int idx = tid + 64 * k;          // 0..127
        int row = idx >> 2, cl = idx & 3;
        g_U[(size_t)panel * 256 + row * 8 + half * 4 + cl] = sC[cl * CCP + row];
    }
}

// ---------------------------------------------------------------------------
// dist_kernel: 512 blocks x 256. GJ-exact yb (single warp), rotate question
// panel, Frobenius distance of the two projectors.
// ---------------------------------------------------------------------------
__global__ __launch_bounds__(256) void dist_kernel(
    const float* __restrict__ bias,
    const float* __restrict__ wf,
    const float* __restrict__ wb,
    float*       __restrict__ out)
{
    const int b   = blockIdx.x;
    const int tid = threadIdx.x;

    __shared__ __align__(16) float sQ [N_DIM * RPAD];
    __shared__ __align__(16) float sCa[N_DIM * RPAD];
    __shared__ __align__(16) float sUq[N_DIM * RPAD];
    __shared__ __align__(16) float syb[N_DIM * CPAD];
    __shared__ float sA8[8 * 16];
    __shared__ float sW8[PQ];
    __shared__ float sbias[PQ];
    __shared__ float red[8];

    {
        int rr = tid >> 3, cc = tid & 7;
        sQ [rr * RPAD + cc] = g_U[(size_t)b * 256 + tid];
        sCa[rr * RPAD + cc] = g_U[(size_t)(BATCH + b) * 256 + tid];
    }
    if (tid < PQ) sbias[tid] = bias[tid];
    __syncthreads();

    // Single-warp Gauss-Jordan on [I + b b^T | I]
    if (tid < 32) {
        int i = tid >> 2, c0 = (tid & 3) * 4;
        #pragma unroll
        for (int m = 0; m < 4; ++m) {
            int cc = c0 + m;
            float v;
            if (cc < 8) {
                v = (i == cc) ? 1.0f : 0.0f;
                #pragma unroll
                for (int k = 0; k < Q_DIM; ++k)
                    v += sbias[i * Q_DIM + k] * sbias[cc * Q_DIM + k];
            } else {
                v = (i == cc - 8) ? 1.0f : 0.0f;
            }
            sA8[i * 16 + cc] = v;
        }
        __syncwarp();
        for (int k = 0; k < 8; ++k) {
            float piv = 1.0f / sA8[k * 16 + k];
            float nv[4];
            #pragma unroll
            for (int m = 0; m < 4; ++m) {
                int cc = c0 + m;
                float akc = sA8[k * 16 + cc] * piv;
                nv[m] = (i == k) ? akc : (sA8[i * 16 + cc] - sA8[i * 16 + k] * akc);
            }
            __syncwarp();
            #pragma unroll
            for (int m = 0; m < 4; ++m) sA8[i * 16 + c0 + m] = nv[m];
            __syncwarp();
        }
    }
    __syncthreads();

    // W = K b
    if (tid < PQ) {
        int i = tid / Q_DIM, jj = tid % Q_DIM;
        float w = 0.0f;
        #pragma unroll
        for (int k = 0; k < 8; ++k) w += sA8[i * 16 + 8 + k] * sbias[k * Q_DIM + jj];
        sW8[tid] = w;
    }
    __syncthreads();

    // yb = [[2K - I, -2W], [2W^T, I - 2 b^T W]]
    #pragma unroll
    for (int e = 0; e < 4; ++e) {
        int idx = tid + 256 * e;
        int rr = idx >> 5, cc = idx & 31;
        float y;
        if (rr < 8 && cc < 8) {
            y = 2.0f * sA8[rr * 16 + 8 + cc] - ((rr == cc) ? 1.0f : 0.0f);
        } else if (rr < 8) {
            y = -2.0f * sW8[rr * Q_DIM + (cc - 8)];
        } else if (cc < 8) {
            y = 2.0f * sW8[cc * Q_DIM + (rr - 8)];
        } else {
            int jj = rr - 8, c2 = cc - 8;
            float acc = 0.0f;
            #pragma unroll
            for (int i = 0; i < 8; ++i) acc += sbias[i * Q_DIM + jj] * sW8[i * Q_DIM + c2];
            y = ((jj == c2) ? 1.0f : 0.0f) - 2.0f * acc;
        }
        syb[rr * CPAD + cc] = y;
    }
    __syncthreads();

    // Uq = yb * Q
    {
        int rr = tid >> 3, cc = tid & 7;
        float acc = 0.0f;
        #pragma unroll
        for (int k = 0; k < N_DIM; ++k)
            acc += syb[rr * CPAD + k] * sQ[k * RPAD + cc];
        sUq[rr * RPAD + cc] = acc;
    }
    __syncthreads();

    // dist^2 = || Uq Uq^T - Ca Ca^T ||_F^2
    float acc = 0.0f;
    #pragma unroll
    for (int e = 0; e < 4; ++e) {
        int idx = tid + 256 * e;
        int i = idx >> 5, jj = idx & 31;
        const float4* ui = (const float4*)(&sUq[i  * RPAD]);
        const float4* uj = (const float4*)(&sUq[jj * RPAD]);
        const float4* ai = (const float4*)(&sCa[i  * RPAD]);
        const float4* aj = (const float4*)(&sCa[jj * RPAD]);
        float d = 0.0f;
        #pragma unroll
        for (int m = 0; m < 2; ++m) {
            float4 a = ui[m], bq = uj[m], x = ai[m], y = aj[m];
            d += a.x * bq.x + a.y * bq.y + a.z * bq.z + a.w * bq.w;
            d -= x.x * y.x  + x.y * y.y  + x.z * y.z  + x.w * y.w;
        }
        acc += d * d;
    }

    #pragma unroll
    for (int off = 16; off > 0; off >>= 1)
        acc += __shfl_xor_sync(0xFFFFFFFFu, acc, off);
    if ((tid & 31) == 0) red[tid >> 5] = acc;
    __syncthreads();
    if (tid == 0) {
        float s = 0.0f;
        #pragma unroll
        for (int w = 0; w < 8; ++w) s += red[w];
        out[b] = -(*wf) * sqrtf(s) + (*wb);
    }
}

// ---------------------------------------------------------------------------
extern "C" void kernel_launch(void* const* d_in, const int* in_sizes, int n_in,
                              void* d_out, int out_size)
{
    const int*   s1 = (const int*)  d_in[0];   // sentence_1 [512,64]
    const int*   s2 = (const int*)  d_in[1];   // sentence_2 [512,64]
    const float* qe = (const float*)d_in[2];   // question_embedding [32000,8,24]
    const float* ae = (const float*)d_in[3];   // answer_embedding   [32000,8,24]
    const float* qt = (const float*)d_in[4];   // question_transforms [8,24]
    const float* qb = (const float*)d_in[5];   // question_bias [8,24]
    const float* wf = (const float*)d_in[6];
    const float* wb = (const float*)d_in[7];
    float* out = (float*)d_out;

    seq_kernel<<<4 * BATCH, 64>>>(s1, s2, qe, ae, qt);
    dist_kernel<<<BATCH, 256>>>(qb, wf, wb, out);
}

// round 11
// speedup vs baseline: 1.1410x; 1.1410x over previous
#include <cuda_runtime.h>
#include <cstdint>

#define BATCH 512
#define TSEQ  64
#define P_DIM 8
#define Q_DIM 24
#define N_DIM 32
#define PQ    (P_DIM * Q_DIM)   // 192
#define CPAD  36                // padded column stride (words) for 32-row panels
#define RPAD  12                // padded row stride for row-major 32x8 panels

// Scratch (no cudaMalloc allowed)
__device__ float g_U[2 * BATCH * N_DIM * P_DIM];  // 1024 x (32x8) row-major panels

// ---- packed f32x2 helpers (Blackwell FFMA2 path; only reachable via PTX) ----
#define FMA2(d, a, b, c) \
    asm("fma.rn.f32x2 %0, %1, %2, %3;" : "=l"(d) : "l"(a), "l"(b), "l"(c))
#define ADD2(d, a, b) \
    asm("add.rn.f32x2 %0, %1, %2;" : "=l"(d) : "l"(a), "l"(b))
#define UNPK2(lo, hi, v) \
    asm("mov.b64 {%0, %1}, %2;" : "=f"(lo), "=f"(hi) : "l"(v))

// ---------------------------------------------------------------------------
// seq_kernel: one 128-thread block per (batch, q/a) panel. 1024 blocks.
//
// Quadratic Cayley recurrence (error 2||X||^3 ~ 1e-6/step):
//   G  = X C ;  C' = C - 2G + 2XG
// X = [[0, x],[-x^T, 0]], x = 8x24. C = 32x8 panel, column-major (CPAD).
//
// Threads: tp < 64 "top" owns entry (r=tp>>3, c=tp&7); tp >= 64 "bottom" owns
// rows 8+3*jg+{0,1,2}, col c. Dot products run on packed f32x2 (FFMA2):
// shared reads come in as ulonglong2 (LDS.128 whose halves are packed pairs).
// ---------------------------------------------------------------------------
__global__ __launch_bounds__(128) void seq_kernel(
    const int*   __restrict__ s1,
    const int*   __restrict__ s2,
    const float* __restrict__ emb_q,
    const float* __restrict__ emb_a,
    const float* __restrict__ transforms)
{
    const int bid   = blockIdx.x;
    const bool is_q = (bid < BATCH);
    const int  b    = is_q ? bid : (bid - BATCH);
    const int  tp   = threadIdx.x;
    const bool top  = (tp < 64);

    const float* emb  = is_q ? emb_q : emb_a;
    const int*   sent = is_q ? s1    : s2;

    __shared__ __align__(16) float sx [2][PQ];   // row-major 8x24
    __shared__ __align__(16) float sxT[2][PQ];   // packed transposed 24x8
    __shared__ __align__(16) float sC[8 * CPAD]; // column-major padded
    __shared__ __align__(16) float sG[8 * CPAD];
    __shared__ int stok[TSEQ];

    // geometry
    const int c  = tp & 7;
    const int r  = tp >> 3;            // top only
    const int jg = (tp - 64) >> 3;     // bottom only
    const int j0 = 3 * jg;

    // x-commit ownership (bank-conflict-free bijection)
    const int i1 = tp & 7;
    const int j1 = tp >> 3;            // 0..15
    const int o1 = i1 * Q_DIM + j1;
    const int ta = j1 * 8 + i1;
    const int j2 = 16 + (tp >> 3);     // top only: 16..23
    const int o2 = i1 * Q_DIM + j2;
    const int tb = j2 * 8 + i1;

    // transform factors (answer: identity)
    float tfa = 1.0f, tfb = 1.0f, tfc = 1.0f, tfd = 1.0f;
    if (is_q) {
        tfa = transforms[tp];
        tfc = transforms[o1];
        if (top) {
            tfb = transforms[tp + 128];
            tfd = transforms[o2];
        }
    }

    if (tp < TSEQ) stok[tp] = sent[b * TSEQ + tp];

    // registers: own panel entries (top uses cown0 only)
    float cown0 = 0.f, cown1 = 0.f, cown2 = 0.f;
    if (top) cown0 = (r == c) ? 1.0f : 0.0f;

    // init shared C
    if (top) {
        sC[c * CPAD + r] = cown0;
    } else {
        sC[c * CPAD + 8 + j0 + 0] = 0.0f;
        sC[c * CPAD + 8 + j0 + 1] = 0.0f;
        sC[c * CPAD + 8 + j0 + 2] = 0.0f;
    }
    __syncthreads();

    // first x (t = 63) into buffer 1, both layouts
    {
        size_t base = (size_t)stok[TSEQ - 1] * PQ;
        sx [1][tp] = emb[base + tp] * tfa;
        sxT[1][ta] = emb[base + o1] * tfc;
        if (top) {
            sx [1][tp + 128] = emb[base + tp + 128] * tfb;
            sxT[1][tb]       = emb[base + o2] * tfd;
        }
    }
    __syncthreads();

    unsigned long long rx2[12];   // 12 packed f32x2 = 24 x-values

    for (int t = TSEQ - 1; t >= 0; --t) {
        const int buf = t & 1;

        // prefetch next token's values (L2-resident after warmup)
        float va = 0.f, vb = 0.f, vc = 0.f, vd = 0.f;
        if (t > 0) {
            size_t base = (size_t)stok[t - 1] * PQ;
            va = emb[base + tp];
            vc = emb[base + o1];
            if (top) {
                vb = emb[base + tp + 128];
                vd = emb[base + o2];
            }
        }

        // cache this step's x slice in packed registers
        if (top) {
            const ulonglong2* px = (const ulonglong2*)(sx[buf] + r * Q_DIM);
            #pragma unroll
            for (int m = 0; m < 6; ++m) {
                ulonglong2 v = px[m];
                rx2[2*m] = v.x; rx2[2*m+1] = v.y;
            }
        } else {
            #pragma unroll
            for (int d = 0; d < 3; ++d) {
                const ulonglong2* pxt = (const ulonglong2*)(sxT[buf] + (j0 + d) * 8);
                ulonglong2 v0 = pxt[0], v1 = pxt[1];
                rx2[d*4+0] = v0.x; rx2[d*4+1] = v0.y;
                rx2[d*4+2] = v1.x; rx2[d*4+3] = v1.y;
            }
        }

        // ---- Phase 1: G = X C
        float gown0, gown1 = 0.f, gown2 = 0.f;
        if (top) {
            const ulonglong2* pc = (const ulonglong2*)(&sC[c * CPAD + 8]);
            unsigned long long a0 = 0ull, a1 = 0ull, a2 = 0ull, a3 = 0ull;
            #pragma unroll
            for (int m = 0; m < 3; ++m) {
                ulonglong2 u = pc[2*m], w = pc[2*m+1];
                FMA2(a0, rx2[4*m+0], u.x, a0);
                FMA2(a1, rx2[4*m+1], u.y, a1);
                FMA2(a2, rx2[4*m+2], w.x, a2);
                FMA2(a3, rx2[4*m+3], w.y, a3);
            }
            ADD2(a0, a0, a1); ADD2(a2, a2, a3); ADD2(a0, a0, a2);
            float lo, hi; UNPK2(lo, hi, a0);
            gown0 = lo + hi;
            sG[c * CPAD + r] = gown0;
        } else {
            const ulonglong2* pc = (const ulonglong2*)(&sC[c * CPAD]);
            ulonglong2 u = pc[0], w = pc[1];
            #pragma unroll
            for (int d = 0; d < 3; ++d) {
                unsigned long long a0 = 0ull, a1 = 0ull;
                FMA2(a0, rx2[d*4+0], u.x, a0);
                FMA2(a1, rx2[d*4+1], u.y, a1);
                FMA2(a0, rx2[d*4+2], w.x, a0);
                FMA2(a1, rx2[d*4+3], w.y, a1);
                ADD2(a0, a0, a1);
                float lo, hi; UNPK2(lo, hi, a0);
                float g = -(lo + hi);
                if (d == 0) gown0 = g; else if (d == 1) gown1 = g; else gown2 = g;
                sG[c * CPAD + 8 + j0 + d] = g;
            }
        }
        __syncthreads();

        // ---- Phase 2: C' = C - 2G + 2XG (in place)
        if (top) {
            const ulonglong2* pg = (const ulonglong2*)(&sG[c * CPAD + 8]);
            unsigned long long a0 = 0ull, a1 = 0ull, a2 = 0ull, a3 = 0ull;
            #pragma unroll
            for (int m = 0; m < 3; ++m) {
                ulonglong2 u = pg[2*m], w = pg[2*m+1];
                FMA2(a0, rx2[4*m+0], u.x, a0);
                FMA2(a1, rx2[4*m+1], u.y, a1);
                FMA2(a2, rx2[4*m+2], w.x, a2);
                FMA2(a3, rx2[4*m+3], w.y, a3);
            }
            ADD2(a0, a0, a1); ADD2(a2, a2, a3); ADD2(a0, a0, a2);
            float lo, hi; UNPK2(lo, hi, a0);
            float h = lo + hi;
            cown0 += 2.0f * (h - gown0);
            sC[c * CPAD + r] = cown0;
        } else {
            const ulonglong2* pg = (const ulonglong2*)(&sG[c * CPAD]);
            ulonglong2 u = pg[0], w = pg[1];
            #pragma unroll
            for (int d = 0; d < 3; ++d) {
                unsigned long long a0 = 0ull, a1 = 0ull;
                FMA2(a0, rx2[d*4+0], u.x, a0);
                FMA2(a1, rx2[d*4+1], u.y, a1);
                FMA2(a0, rx2[d*4+2], w.x, a0);
                FMA2(a1, rx2[d*4+3], w.y, a1);
                ADD2(a0, a0, a1);
                float lo, hi; UNPK2(lo, hi, a0);
                float h = -(lo + hi);
                float go = (d == 0) ? gown0 : ((d == 1) ? gown1 : gown2);
                float cn = ((d == 0) ? cown0 : ((d == 1) ? cown1 : cown2)) + 2.0f * (h - go);
                if (d == 0) cown0 = cn; else if (d == 1) cown1 = cn; else cown2 = cn;
                sC[c * CPAD + 8 + j0 + d] = cn;
            }
        }

        // commit next x into the other buffer (both layouts)
        if (t > 0) {
            const int nb = buf ^ 1;
            sx [nb][tp] = va * tfa;
            sxT[nb][ta] = vc * tfc;
            if (top) {
                sx [nb][tp + 128] = vb * tfb;
                sxT[nb][tb]       = vd * tfd;
            }
        }
        __syncthreads();
    }

    // write final panel row-major to global
    {
        int idx = tp;
        g_U[(size_t)bid * 256 + idx] = sC[(idx & 7) * CPAD + (idx >> 3)];
        idx = tp + 128;
        g_U[(size_t)bid * 256 + idx] = sC[(idx & 7) * CPAD + (idx >> 3)];
    }
}

// ---------------------------------------------------------------------------
// dist_kernel: 512 blocks x 256. Per block: GJ-exact yb (redundant), rotate
// the question panel, Frobenius distance of the two projectors.
// ---------------------------------------------------------------------------
__global__ __launch_bounds__(256) void dist_kernel(
    const float* __restrict__ bias,
    const float* __restrict__ wf,
    const float* __restrict__ wb,
    float*       __restrict__ out)
{
    const int b   = blockIdx.x;
    const int tid = threadIdx.x;

    __shared__ __align__(16) float sQ [N_DIM * RPAD];
    __shared__ __align__(16) float sCa[N_DIM * RPAD];
    __shared__ __align__(16) float sUq[N_DIM * RPAD];
    __shared__ __align__(16) float syb[N_DIM * CPAD];
    __shared__ float sA8[8 * 16];
    __shared__ float sW8[PQ];
    __shared__ float sbias[PQ];
    __shared__ float red[8];

    {
        int rr = tid >> 3, cc = tid & 7;
        sQ [rr * RPAD + cc] = g_U[(size_t)b * 256 + tid];
        sCa[rr * RPAD + cc] = g_U[(size_t)(BATCH + b) * 256 + tid];
    }
    if (tid < PQ) sbias[tid] = bias[tid];
    __syncthreads();

    // A = [I + b b^T | I]
    if (tid < 128) {
        int i = tid >> 4, cc = tid & 15;
        float v;
        if (cc < 8) {
            v = (i == cc) ? 1.0f : 0.0f;
            #pragma unroll
            for (int k = 0; k < Q_DIM; ++k) v += sbias[i * Q_DIM + k] * sbias[cc * Q_DIM + k];
        } else {
            v = (i == cc - 8) ? 1.0f : 0.0f;
        }
        sA8[i * 16 + cc] = v;
    }
    __syncthreads();

    // Gauss-Jordan
    for (int k = 0; k < 8; ++k) {
        float nv = 0.0f;
        int i = tid >> 4, cc = tid & 15;
        if (tid < 128) {
            float piv = 1.0f / sA8[k * 16 + k];
            float akc = sA8[k * 16 + cc] * piv;
            nv = (i == k) ? akc : (sA8[i * 16 + cc] - sA8[i * 16 + k] * akc);
        }
        __syncthreads();
        if (tid < 128) sA8[i * 16 + cc] = nv;
        __syncthreads();
    }

    // W = K b
    if (tid < PQ) {
        int i = tid / Q_DIM, jj = tid % Q_DIM;
        float w = 0.0f;
        #pragma unroll
        for (int k = 0; k < 8; ++k) w += sA8[i * 16 + 8 + k] * sbias[k * Q_DIM + jj];
        sW8[tid] = w;
    }
    __syncthreads();

    // yb = [[2K - I, -2W], [2W^T, I - 2 b^T W]]
    #pragma unroll
    for (int e = 0; e < 4; ++e) {
        int idx = tid + 256 * e;
        int rr = idx >> 5, cc = idx & 31;
        float y;
        if (rr < 8 && cc < 8) {
            y = 2.0f * sA8[rr * 16 + 8 + cc] - ((rr == cc) ? 1.0f : 0.0f);
        } else if (rr < 8) {
            y = -2.0f * sW8[rr * Q_DIM + (cc - 8)];
        } else if (cc < 8) {
            y = 2.0f * sW8[cc * Q_DIM + (rr - 8)];
        } else {
            int jj = rr - 8, c2 = cc - 8;
            float acc = 0.0f;
            #pragma unroll
            for (int i = 0; i < 8; ++i) acc += sbias[i * Q_DIM + jj] * sW8[i * Q_DIM + c2];
            y = ((jj == c2) ? 1.0f : 0.0f) - 2.0f * acc;
        }
        syb[rr * CPAD + cc] = y;
    }
    __syncthreads();

    // Uq = yb * Q
    {
        int rr = tid >> 3, cc = tid & 7;
        float acc = 0.0f;
        #pragma unroll
        for (int k = 0; k < N_DIM; ++k)
            acc += syb[rr * CPAD + k] * sQ[k * RPAD + cc];
        sUq[rr * RPAD + cc] = acc;
    }
    __syncthreads();

    // dist^2 = || Uq Uq^T - Ca Ca^T ||_F^2
    float acc = 0.0f;
    #pragma unroll
    for (int e = 0; e < 4; ++e) {
        int idx = tid + 256 * e;
        int i = idx >> 5, jj = idx & 31;
        const float4* ui = (const float4*)(&sUq[i  * RPAD]);
        const float4* uj = (const float4*)(&sUq[jj * RPAD]);
        const float4* ai = (const float4*)(&sCa[i  * RPAD]);
        const float4* aj = (const float4*)(&sCa[jj * RPAD]);
        float d = 0.0f;
        #pragma unroll
        for (int m = 0; m < 2; ++m) {
            float4 a = ui[m], bq = uj[m], x = ai[m], y = aj[m];
            d += a.x * bq.x + a.y * bq.y + a.z * bq.z + a.w * bq.w;
            d -= x.x * y.x  + x.y * y.y  + x.z * y.z  + x.w * y.w;
        }
        acc += d * d;
    }

    #pragma unroll
    for (int off = 16; off > 0; off >>= 1)
        acc += __shfl_xor_sync(0xFFFFFFFFu, acc, off);
    if ((tid & 31) == 0) red[tid >> 5] = acc;
    __syncthreads();
    if (tid == 0) {
        float s = 0.0f;
        #pragma unroll
        for (int w = 0; w < 8; ++w) s += red[w];
        out[b] = -(*wf) * sqrtf(s) + (*wb);
    }
}

// ---------------------------------------------------------------------------
extern "C" void kernel_launch(void* const* d_in, const int* in_sizes, int n_in,
                              void* d_out, int out_size)
{
    const int*   s1 = (const int*)  d_in[0];   // sentence_1 [512,64]
    const int*   s2 = (const int*)  d_in[1];   // sentence_2 [512,64]
    const float* qe = (const float*)d_in[2];   // question_embedding [32000,8,24]
    const float* ae = (const float*)d_in[3];   // answer_embedding   [32000,8,24]
    const float* qt = (const float*)d_in[4];   // question_transforms [8,24]
    const float* qb = (const float*)d_in[5];   // question_bias [8,24]
    const float* wf = (const float*)d_in[6];
    const float* wb = (const float*)d_in[7];
    float* out = (float*)d_out;

    seq_kernel<<<2 * BATCH, 128>>>(s1, s2, qe, ae, qt);
    dist_kernel<<<BATCH, 256>>>(qb, wf, wb, out);
}

// round 12
// speedup vs baseline: 1.2110x; 1.0614x over previous
#include <cuda_runtime.h>
#include <cstdint>

#define BATCH 512
#define TSEQ  64
#define P_DIM 8
#define Q_DIM 24
#define N_DIM 32
#define PQ    (P_DIM * Q_DIM)   // 192
#define CPAD  36                // padded column stride (words) for 32-row panels
#define RPAD  12                // padded row stride for row-major 32x8 panels

// Scratch (no cudaMalloc allowed)
__device__ float g_U[2 * BATCH * N_DIM * P_DIM];  // 1024 x (32x8) row-major panels
__device__ int   g_cnt[BATCH];                    // arrival counters (parity-based, never reset)

// ---------------------------------------------------------------------------
// seq_kernel: one 128-thread block per (batch, q/a) panel. 1024 blocks.
//
// Quadratic Cayley recurrence (error 2||X||^3 ~ 1e-6/step):
//   G  = X C ;  C' = C - 2G + 2XG
// X = [[0, x],[-x^T, 0]], x = 8x24. C = 32x8 panel, column-major (CPAD).
//
// Threads: tp < 64 "top" owns entry (r=tp>>3, c=tp&7); tp >= 64 "bottom" owns
// rows 8+3*jg+{0,1,2}, col c. x kept in shared in BOTH layouts (row-major sx
// for top, packed transposed sxT for bottom), double-buffered; all loop
// LDS/STS are bank-conflict-free.
//
// Tail: second block of each batch (atomic parity) computes the distance.
// ---------------------------------------------------------------------------
__global__ __launch_bounds__(128) void seq_kernel(
    const int*   __restrict__ s1,
    const int*   __restrict__ s2,
    const float* __restrict__ emb_q,
    const float* __restrict__ emb_a,
    const float* __restrict__ transforms,
    const float* __restrict__ bias,
    const float* __restrict__ wf,
    const float* __restrict__ wb,
    float*       __restrict__ out)
{
    const int bid   = blockIdx.x;
    const bool is_q = (bid < BATCH);
    const int  b    = is_q ? bid : (bid - BATCH);
    const int  tp   = threadIdx.x;
    const bool top  = (tp < 64);

    const float* emb  = is_q ? emb_q : emb_a;
    const int*   sent = is_q ? s1    : s2;

    __shared__ __align__(16) float sx [2][PQ];   // row-major 8x24
    __shared__ __align__(16) float sxT[2][PQ];   // packed transposed 24x8
    __shared__ __align__(16) float sC[8 * CPAD]; // column-major padded
    __shared__ __align__(16) float sG[8 * CPAD];
    __shared__ int stok[TSEQ];
    // tail scratch
    __shared__ __align__(16) float sQ [N_DIM * RPAD];
    __shared__ __align__(16) float sCa[N_DIM * RPAD];
    __shared__ __align__(16) float sUq[N_DIM * RPAD];
    __shared__ __align__(16) float syb[N_DIM * CPAD];
    __shared__ float sA8[8 * 16];
    __shared__ float sW8[PQ];
    __shared__ float sbias[PQ];
    __shared__ float red[4];
    __shared__ int   s_old;

    // geometry
    const int c  = tp & 7;
    const int r  = tp >> 3;            // top only
    const int jg = (tp - 64) >> 3;     // bottom only
    const int j0 = 3 * jg;

    // x-commit ownership (bank-conflict-free bijection)
    const int i1 = tp & 7;
    const int j1 = tp >> 3;            // 0..15
    const int o1 = i1 * Q_DIM + j1;
    const int ta = j1 * 8 + i1;
    const int j2 = 16 + (tp >> 3);     // top only: 16..23
    const int o2 = i1 * Q_DIM + j2;
    const int tb = j2 * 8 + i1;

    // transform factors (answer: identity)
    float tfa = 1.0f, tfb = 1.0f, tfc = 1.0f, tfd = 1.0f;
    if (is_q) {
        tfa = transforms[tp];
        tfc = transforms[o1];
        if (top) {
            tfb = transforms[tp + 128];
            tfd = transforms[o2];
        }
    }

    if (tp < TSEQ) stok[tp] = sent[b * TSEQ + tp];

    // registers: own panel entries (top uses cown0 only)
    float cown0 = 0.f, cown1 = 0.f, cown2 = 0.f;
    if (top) cown0 = (r == c) ? 1.0f : 0.0f;

    // init shared C
    if (top) {
        sC[c * CPAD + r] = cown0;
    } else {
        sC[c * CPAD + 8 + j0 + 0] = 0.0f;
        sC[c * CPAD + 8 + j0 + 1] = 0.0f;
        sC[c * CPAD + 8 + j0 + 2] = 0.0f;
    }
    __syncthreads();

    // first x (t = 63) into buffer 1, both layouts
    {
        size_t base = (size_t)stok[TSEQ - 1] * PQ;
        sx [1][tp] = emb[base + tp] * tfa;
        sxT[1][ta] = emb[base + o1] * tfc;
        if (top) {
            sx [1][tp + 128] = emb[base + tp + 128] * tfb;
            sxT[1][tb]       = emb[base + o2] * tfd;
        }
    }
    __syncthreads();

    float rx[24];

    for (int t = TSEQ - 1; t >= 0; --t) {
        const int buf = t & 1;

        // prefetch next token's values (L2-resident after warmup)
        float va = 0.f, vb = 0.f, vc = 0.f, vd = 0.f;
        if (t > 0) {
            size_t base = (size_t)stok[t - 1] * PQ;
            va = emb[base + tp];
            vc = emb[base + o1];
            if (top) {
                vb = emb[base + tp + 128];
                vd = emb[base + o2];
            }
        }

        // cache this step's x slice in registers
        if (top) {
            const float4* px = (const float4*)(sx[buf] + r * Q_DIM);
            #pragma unroll
            for (int m = 0; m < 6; ++m) {
                float4 v = px[m];
                rx[4*m] = v.x; rx[4*m+1] = v.y; rx[4*m+2] = v.z; rx[4*m+3] = v.w;
            }
        } else {
            #pragma unroll
            for (int d = 0; d < 3; ++d) {
                const float4* pxt = (const float4*)(sxT[buf] + (j0 + d) * 8);
                float4 v0 = pxt[0], v1 = pxt[1];
                rx[d*8+0] = v0.x; rx[d*8+1] = v0.y; rx[d*8+2] = v0.z; rx[d*8+3] = v0.w;
                rx[d*8+4] = v1.x; rx[d*8+5] = v1.y; rx[d*8+6] = v1.z; rx[d*8+7] = v1.w;
            }
        }

        // ---- Phase 1: G = X C
        float gown0, gown1 = 0.f, gown2 = 0.f;
        if (top) {
            const float4* pc = (const float4*)(&sC[c * CPAD + 8]);
            float a0 = 0.f, a1 = 0.f, a2 = 0.f, a3 = 0.f;
            #pragma unroll
            for (int m = 0; m < 6; ++m) {
                float4 v = pc[m];
                a0 += rx[4*m] * v.x;  a1 += rx[4*m+1] * v.y;
                a2 += rx[4*m+2] * v.z; a3 += rx[4*m+3] * v.w;
            }
            gown0 = (a0 + a1) + (a2 + a3);
            sG[c * CPAD + r] = gown0;
        } else {
            const float4* pc = (const float4*)(&sC[c * CPAD]);
            float4 v0 = pc[0], v1 = pc[1];
            #pragma unroll
            for (int d = 0; d < 3; ++d) {
                float g = rx[d*8+0]*v0.x + rx[d*8+1]*v0.y + rx[d*8+2]*v0.z + rx[d*8+3]*v0.w
                        + rx[d*8+4]*v1.x + rx[d*8+5]*v1.y + rx[d*8+6]*v1.z + rx[d*8+7]*v1.w;
                g = -g;
                if (d == 0) gown0 = g; else if (d == 1) gown1 = g; else gown2 = g;
                sG[c * CPAD + 8 + j0 + d] = g;
            }
        }
        __syncthreads();

        // ---- Phase 2: C' = C - 2G + 2XG (in place)
        if (top) {
            const float4* pg = (const float4*)(&sG[c * CPAD + 8]);
            float a0 = 0.f, a1 = 0.f, a2 = 0.f, a3 = 0.f;
            #pragma unroll
            for (int m = 0; m < 6; ++m) {
                float4 v = pg[m];
                a0 += rx[4*m] * v.x;  a1 += rx[4*m+1] * v.y;
                a2 += rx[4*m+2] * v.z; a3 += rx[4*m+3] * v.w;
            }
            float h = (a0 + a1) + (a2 + a3);
            cown0 += 2.0f * (h - gown0);
            sC[c * CPAD + r] = cown0;
        } else {
            const float4* pg = (const float4*)(&sG[c * CPAD]);
            float4 v0 = pg[0], v1 = pg[1];
            #pragma unroll
            for (int d = 0; d < 3; ++d) {
                float h = rx[d*8+0]*v0.x + rx[d*8+1]*v0.y + rx[d*8+2]*v0.z + rx[d*8+3]*v0.w
                        + rx[d*8+4]*v1.x + rx[d*8+5]*v1.y + rx[d*8+6]*v1.z + rx[d*8+7]*v1.w;
                h = -h;
                float go = (d == 0) ? gown0 : ((d == 1) ? gown1 : gown2);
                float cn = ((d == 0) ? cown0 : ((d == 1) ? cown1 : cown2)) + 2.0f * (h - go);
                if (d == 0) cown0 = cn; else if (d == 1) cown1 = cn; else cown2 = cn;
                sC[c * CPAD + 8 + j0 + d] = cn;
            }
        }

        // commit next x into the other buffer (both layouts)
        if (t > 0) {
            const int nb = buf ^ 1;
            sx [nb][tp] = va * tfa;
            sxT[nb][ta] = vc * tfc;
            if (top) {
                sx [nb][tp + 128] = vb * tfb;
                sxT[nb][tb]       = vd * tfd;
            }
        }
        __syncthreads();
    }

    // write final panel row-major to global
    {
        int idx = tp;
        g_U[(size_t)bid * 256 + idx] = sC[(idx & 7) * CPAD + (idx >> 3)];
        idx = tp + 128;
        g_U[(size_t)bid * 256 + idx] = sC[(idx & 7) * CPAD + (idx >> 3)];
    }

    // ---- arrival protocol: second block of this batch runs the distance tail
    __threadfence();              // release g_U writes
    __syncthreads();
    if (tp == 0) s_old = atomicAdd(&g_cnt[b], 1);
    __syncthreads();
    if ((s_old & 1) == 0) return; // first arrival: done
    __threadfence();              // acquire peer's g_U writes

    // =====================  DISTANCE TAIL (128 threads)  =====================
    // load both panels (row-major idx = r*8+c)
    #pragma unroll
    for (int k = 0; k < 2; ++k) {
        int idx = tp + 128 * k;
        int rr = idx >> 3, cc = idx & 7;
        sQ [rr * RPAD + cc] = g_U[(size_t)b * 256 + idx];
        sCa[rr * RPAD + cc] = g_U[(size_t)(BATCH + b) * 256 + idx];
    }
    for (int i = tp; i < PQ; i += 128) sbias[i] = bias[i];
    __syncthreads();

    // A = [I + b b^T | I]
    {
        int i = tp >> 4, cc = tp & 15;
        float v;
        if (cc < 8) {
            v = (i == cc) ? 1.0f : 0.0f;
            #pragma unroll
            for (int k = 0; k < Q_DIM; ++k) v += sbias[i * Q_DIM + k] * sbias[cc * Q_DIM + k];
        } else {
            v = (i == cc - 8) ? 1.0f : 0.0f;
        }
        sA8[i * 16 + cc] = v;
    }
    __syncthreads();

    // Gauss-Jordan (SPD, pivots >= 1)
    for (int k = 0; k < 8; ++k) {
        int i = tp >> 4, cc = tp & 15;
        float piv = 1.0f / sA8[k * 16 + k];
        float akc = sA8[k * 16 + cc] * piv;
        float nv = (i == k) ? akc : (sA8[i * 16 + cc] - sA8[i * 16 + k] * akc);
        __syncthreads();
        sA8[i * 16 + cc] = nv;
        __syncthreads();
    }

    // W = K b
    for (int idx = tp; idx < PQ; idx += 128) {
        int i = idx / Q_DIM, jj = idx % Q_DIM;
        float w = 0.0f;
        #pragma unroll
        for (int k = 0; k < 8; ++k) w += sA8[i * 16 + 8 + k] * sbias[k * Q_DIM + jj];
        sW8[idx] = w;
    }
    __syncthreads();

    // yb = [[2K - I, -2W], [2W^T, I - 2 b^T W]]
    #pragma unroll
    for (int e = 0; e < 8; ++e) {
        int idx = tp + 128 * e;
        int rr = idx >> 5, cc = idx & 31;
        float y;
        if (rr < 8 && cc < 8) {
            y = 2.0f * sA8[rr * 16 + 8 + cc] - ((rr == cc) ? 1.0f : 0.0f);
        } else if (rr < 8) {
            y = -2.0f * sW8[rr * Q_DIM + (cc - 8)];
        } else if (cc < 8) {
            y = 2.0f * sW8[cc * Q_DIM + (rr - 8)];
        } else {
            int jj = rr - 8, c2 = cc - 8;
            float acc = 0.0f;
            #pragma unroll
            for (int i = 0; i < 8; ++i) acc += sbias[i * Q_DIM + jj] * sW8[i * Q_DIM + c2];
            y = ((jj == c2) ? 1.0f : 0.0f) - 2.0f * acc;
        }
        syb[rr * CPAD + cc] = y;
    }
    __syncthreads();

    // Uq = yb * Q
    #pragma unroll
    for (int k2 = 0; k2 < 2; ++k2) {
        int idx = tp + 128 * k2;
        int rr = idx >> 3, cc = idx & 7;
        float acc = 0.0f;
        #pragma unroll
        for (int k = 0; k < N_DIM; ++k)
            acc += syb[rr * CPAD + k] * sQ[k * RPAD + cc];
        sUq[rr * RPAD + cc] = acc;
    }
    __syncthreads();

    // dist^2 = || Uq Uq^T - Ca Ca^T ||_F^2
    float acc = 0.0f;
    #pragma unroll
    for (int e = 0; e < 8; ++e) {
        int idx = tp + 128 * e;
        int i = idx >> 5, jj = idx & 31;
        const float4* ui = (const float4*)(&sUq[i  * RPAD]);
        const float4* uj = (const float4*)(&sUq[jj * RPAD]);
        const float4* ai = (const float4*)(&sCa[i  * RPAD]);
        const float4* aj = (const float4*)(&sCa[jj * RPAD]);
        float d = 0.0f;
        #pragma unroll
        for (int m = 0; m < 2; ++m) {
            float4 a = ui[m], bq = uj[m], x = ai[m], y = aj[m];
            d += a.x * bq.x + a.y * bq.y + a.z * bq.z + a.w * bq.w;
            d -= x.x * y.x  + x.y * y.y  + x.z * y.z  + x.w * y.w;
        }
        acc += d * d;
    }

    #pragma unroll
    for (int off = 16; off > 0; off >>= 1)
        acc += __shfl_xor_sync(0xFFFFFFFFu, acc, off);
    if ((tp & 31) == 0) red[tp >> 5] = acc;
    __syncthreads();
    if (tp == 0) {
        float s = red[0] + red[1] + red[2] + red[3];
        out[b] = -(*wf) * sqrtf(s) + (*wb);
    }
}

// ---------------------------------------------------------------------------
extern "C" void kernel_launch(void* const* d_in, const int* in_sizes, int n_in,
                              void* d_out, int out_size)
{
    const int*   s1 = (const int*)  d_in[0];   // sentence_1 [512,64]
    const int*   s2 = (const int*)  d_in[1];   // sentence_2 [512,64]
    const float* qe = (const float*)d_in[2];   // question_embedding [32000,8,24]
    const float* ae = (const float*)d_in[3];   // answer_embedding   [32000,8,24]
    const float* qt = (const float*)d_in[4];   // question_transforms [8,24]
    const float* qb = (const float*)d_in[5];   // question_bias [8,24]
    const float* wf = (const float*)d_in[6];
    const float* wb = (const float*)d_in[7];
    float* out = (float*)d_out;

    seq_kernel<<<2 * BATCH, 128>>>(s1, s2, qe, ae, qt, qb, wf, wb, out);
}

// round 13
// speedup vs baseline: 1.2292x; 1.0150x over previous
#include <cuda_runtime.h>
#include <cstdint>

#define BATCH 512
#define TSEQ  64
#define P_DIM 8
#define Q_DIM 24
#define N_DIM 32
#define PQ    (P_DIM * Q_DIM)   // 192
#define SXP   28                // padded row stride for sx (8 x 28)
#define CPAD  36                // padded column stride (words) for 32-row panels
#define RPAD  12                // padded row stride for row-major 32x8 panels

// Scratch (no cudaMalloc allowed)
__device__ float g_U[2 * BATCH * N_DIM * P_DIM];  // 1024 x (32x8) row-major panels
__device__ int   g_cnt[BATCH];                    // arrival counters (parity, never reset)

// ---------------------------------------------------------------------------
// seq_kernel: one 128-thread block per (batch, q/a) panel. 1024 blocks.
//
// Quadratic Cayley recurrence (error 2||X||^3 ~ 1e-6/step):
//   G  = X C ;  C' = C - 2G + 2XG
// X = [[0, x],[-x^T, 0]], x = 8x24. C = 32x8 panel, column-major (CPAD).
//
// tp < 64 "top" owns entry (r=tp>>3, c=tp&7); tp >= 64 "bottom" owns rows
// 8+3*jg+{0,1,2}, col c. x staged in shared in BOTH layouts from a single
// gather set (each thread loads o1 [+o2 for top], stores to sx and sxT).
// 2-step unroll makes all shared addresses loop-invariant.
// Tail: second block of each batch (atomic parity) computes the distance.
// ---------------------------------------------------------------------------
__global__ __launch_bounds__(128) void seq_kernel(
    const int*   __restrict__ s1,
    const int*   __restrict__ s2,
    const float* __restrict__ emb_q,
    const float* __restrict__ emb_a,
    const float* __restrict__ transforms,
    const float* __restrict__ bias,
    const float* __restrict__ wf,
    const float* __restrict__ wb,
    float*       __restrict__ out)
{
    const int bid   = blockIdx.x;
    const bool is_q = (bid < BATCH);
    const int  b    = is_q ? bid : (bid - BATCH);
    const int  tp   = threadIdx.x;
    const bool top  = (tp < 64);

    const float* emb  = is_q ? emb_q : emb_a;
    const int*   sent = is_q ? s1    : s2;

    __shared__ __align__(16) float sx [2][8 * SXP];  // row-major padded 8x28
    __shared__ __align__(16) float sxT[2][PQ];       // packed transposed 24x8
    __shared__ __align__(16) float sC[8 * CPAD];     // column-major padded
    __shared__ __align__(16) float sG[8 * CPAD];
    __shared__ int stok[TSEQ];                       // token BYTE offsets
    // tail scratch
    __shared__ __align__(16) float sQ [N_DIM * RPAD];
    __shared__ __align__(16) float sCa[N_DIM * RPAD];
    __shared__ __align__(16) float sUq[N_DIM * RPAD];
    __shared__ __align__(16) float syb[N_DIM * CPAD];
    __shared__ float sA8[8 * 16];
    __shared__ float sW8[PQ];
    __shared__ float sbias[PQ];
    __shared__ float red[4];
    __shared__ int   s_old;

    // geometry
    const int c  = tp & 7;
    const int r  = tp >> 3;            // top only
    const int jg = (tp - 64) >> 3;     // bottom only
    const int j0 = 3 * jg;

    // x gather/commit ownership (bank-conflict-free bijections)
    const int i1 = tp & 7;
    const int j1 = tp >> 3;            // 0..15
    const int o1 = i1 * Q_DIM + j1;    // gathered element 1 (row-major index)
    const int sxA = i1 * SXP + j1;     // sx addr 1
    const int ta  = j1 * 8 + i1;       // sxT addr 1
    const int j2 = 16 + (tp >> 3);     // top only: 16..23
    const int o2 = i1 * Q_DIM + j2;
    const int sxB = i1 * SXP + j2;
    const int tb  = j2 * 8 + i1;

    // transform factors on the gathered elements (answer: identity)
    float tfc = 1.0f, tfd = 1.0f;
    if (is_q) {
        tfc = transforms[o1];
        if (top) tfd = transforms[o2];
    }

    // element pointers (byte-offset addressing per step)
    const char* pe1 = (const char*)(emb + o1);
    const char* pe2 = (const char*)(emb + o2);

    if (tp < TSEQ) stok[tp] = sent[b * TSEQ + tp] * (PQ * 4);

    // registers: own panel entries (top uses cown0 only)
    float cown0 = 0.f, cown1 = 0.f, cown2 = 0.f;
    if (top) cown0 = (r == c) ? 1.0f : 0.0f;

    // init shared C
    if (top) {
        sC[c * CPAD + r] = cown0;
    } else {
        sC[c * CPAD + 8 + j0 + 0] = 0.0f;
        sC[c * CPAD + 8 + j0 + 1] = 0.0f;
        sC[c * CPAD + 8 + j0 + 2] = 0.0f;
    }
    __syncthreads();

    // first x (t = 63) into buffer 1, both layouts from the gather set
    {
        int off = stok[TSEQ - 1];
        float vc = *(const float*)(pe1 + off) * tfc;
        sx [1][sxA] = vc;
        sxT[1][ta]  = vc;
        if (top) {
            float vd = *(const float*)(pe2 + off) * tfd;
            sx [1][sxB] = vd;
            sxT[1][tb]  = vd;
        }
    }
    __syncthreads();

    float rx[24];

#define SEQ_STEP(BUF, T)                                                        \
    do {                                                                        \
        float vc = 0.f, vd = 0.f;                                               \
        if ((T) > 0) {                                                          \
            int off = stok[(T) - 1];                                            \
            vc = *(const float*)(pe1 + off);                                    \
            if (top) vd = *(const float*)(pe2 + off);                           \
        }                                                                       \
        if (top) {                                                              \
            const float4* px = (const float4*)(sx[BUF] + r * SXP);              \
            _Pragma("unroll")                                                   \
            for (int m = 0; m < 6; ++m) {                                       \
                float4 v = px[m];                                               \
                rx[4*m]=v.x; rx[4*m+1]=v.y; rx[4*m+2]=v.z; rx[4*m+3]=v.w;       \
            }                                                                   \
        } else {                                                                \
            _Pragma("unroll")                                                   \
            for (int d = 0; d < 3; ++d) {                                       \
                const float4* pxt = (const float4*)(sxT[BUF] + (j0 + d) * 8);   \
                float4 v0 = pxt[0], v1 = pxt[1];                                \
                rx[d*8+0]=v0.x; rx[d*8+1]=v0.y; rx[d*8+2]=v0.z; rx[d*8+3]=v0.w; \
                rx[d*8+4]=v1.x; rx[d*8+5]=v1.y; rx[d*8+6]=v1.z; rx[d*8+7]=v1.w; \
            }                                                                   \
        }                                                                       \
        float gown0, gown1 = 0.f, gown2 = 0.f;                                  \
        if (top) {                                                              \
            const float4* pc = (const float4*)(&sC[c * CPAD + 8]);              \
            float a0=0.f,a1=0.f,a2=0.f,a3=0.f;                                  \
            _Pragma("unroll")                                                   \
            for (int m = 0; m < 6; ++m) {                                       \
                float4 v = pc[m];                                               \
                a0 += rx[4*m]*v.x;  a1 += rx[4*m+1]*v.y;                        \
                a2 += rx[4*m+2]*v.z; a3 += rx[4*m+3]*v.w;                       \
            }                                                                   \
            gown0 = (a0 + a1) + (a2 + a3);                                      \
            sG[c * CPAD + r] = gown0;                                           \
        } else {                                                                \
            const float4* pc = (const float4*)(&sC[c * CPAD]);                  \
            float4 v0 = pc[0], v1 = pc[1];                                      \
            _Pragma("unroll")                                                   \
            for (int d = 0; d < 3; ++d) {                                       \
                float g = rx[d*8+0]*v0.x + rx[d*8+1]*v0.y + rx[d*8+2]*v0.z      \
                        + rx[d*8+3]*v0.w + rx[d*8+4]*v1.x + rx[d*8+5]*v1.y      \
                        + rx[d*8+6]*v1.z + rx[d*8+7]*v1.w;                      \
                g = -g;                                                         \
                if (d == 0) gown0 = g; else if (d == 1) gown1 = g; else gown2 = g;\
                sG[c * CPAD + 8 + j0 + d] = g;                                  \
            }                                                                   \
        }                                                                       \
        __syncthreads();                                                        \
        if (top) {                                                              \
            const float4* pg = (const float4*)(&sG[c * CPAD + 8]);              \
            float a0=0.f,a1=0.f,a2=0.f,a3=0.f;                                  \
            _Pragma("unroll")                                                   \
            for (int m = 0; m < 6; ++m) {                                       \
                float4 v = pg[m];                                               \
                a0 += rx[4*m]*v.x;  a1 += rx[4*m+1]*v.y;                        \
                a2 += rx[4*m+2]*v.z; a3 += rx[4*m+3]*v.w;                       \
            }                                                                   \
            float h = (a0 + a1) + (a2 + a3);                                    \
            cown0 += 2.0f * (h - gown0);                                        \
            sC[c * CPAD + r] = cown0;                                           \
        } else {                                                                \
            const float4* pg = (const float4*)(&sG[c * CPAD]);                  \
            float4 v0 = pg[0], v1 = pg[1];                                      \
            _Pragma("unroll")                                                   \
            for (int d = 0; d < 3; ++d) {                                       \
                float h = rx[d*8+0]*v0.x + rx[d*8+1]*v0.y + rx[d*8+2]*v0.z      \
                        + rx[d*8+3]*v0.w + rx[d*8+4]*v1.x + rx[d*8+5]*v1.y      \
                        + rx[d*8+6]*v1.z + rx[d*8+7]*v1.w;                      \
                h = -h;                                                         \
                float go = (d == 0) ? gown0 : ((d == 1) ? gown1 : gown2);       \
                float cn = ((d == 0) ? cown0 : ((d == 1) ? cown1 : cown2))      \
                           + 2.0f * (h - go);                                   \
                if (d == 0) cown0 = cn; else if (d == 1) cown1 = cn; else cown2 = cn;\
                sC[c * CPAD + 8 + j0 + d] = cn;                                 \
            }                                                                   \
        }                                                                       \
        if ((T) > 0) {                                                          \
            float wc = vc * tfc;                                                \
            sx [(BUF)^1][sxA] = wc;                                             \
            sxT[(BUF)^1][ta]  = wc;                                             \
            if (top) {                                                          \
                float wd = vd * tfd;                                            \
                sx [(BUF)^1][sxB] = wd;                                         \
                sxT[(BUF)^1][tb]  = wd;                                         \
            }                                                                   \
        }                                                                       \
        __syncthreads();                                                        \
    } while (0)

    for (int t2 = 31; t2 >= 0; --t2) {
        SEQ_STEP(1, 2 * t2 + 1);
        SEQ_STEP(0, 2 * t2);
    }
#undef SEQ_STEP

    // write final panel row-major to global
    {
        int idx = tp;
        g_U[(size_t)bid * 256 + idx] = sC[(idx & 7) * CPAD + (idx >> 3)];
        idx = tp + 128;
        g_U[(size_t)bid * 256 + idx] = sC[(idx & 7) * CPAD + (idx >> 3)];
    }

    // ---- arrival protocol: second block of this batch runs the distance tail
    __threadfence();              // release g_U writes
    __syncthreads();
    if (tp == 0) s_old = atomicAdd(&g_cnt[b], 1);
    __syncthreads();
    if ((s_old & 1) == 0) return; // first arrival: done
    __threadfence();              // acquire peer's g_U writes

    // =====================  DISTANCE TAIL (128 threads)  =====================
    #pragma unroll
    for (int k = 0; k < 2; ++k) {
        int idx = tp + 128 * k;
        int rr = idx >> 3, cc = idx & 7;
        sQ [rr * RPAD + cc] = g_U[(size_t)b * 256 + idx];
        sCa[rr * RPAD + cc] = g_U[(size_t)(BATCH + b) * 256 + idx];
    }
    for (int i = tp; i < PQ; i += 128) sbias[i] = bias[i];
    __syncthreads();

    // A = [I + b b^T | I]
    {
        int i = tp >> 4, cc = tp & 15;
        float v;
        if (cc < 8) {
            v = (i == cc) ? 1.0f : 0.0f;
            #pragma unroll
            for (int k = 0; k < Q_DIM; ++k) v += sbias[i * Q_DIM + k] * sbias[cc * Q_DIM + k];
        } else {
            v = (i == cc - 8) ? 1.0f : 0.0f;
        }
        sA8[i * 16 + cc] = v;
    }
    __syncthreads();

    // Gauss-Jordan (SPD, pivots >= 1)
    for (int k = 0; k < 8; ++k) {
        int i = tp >> 4, cc = tp & 15;
        float piv = 1.0f / sA8[k * 16 + k];
        float akc = sA8[k * 16 + cc] * piv;
        float nv = (i == k) ? akc : (sA8[i * 16 + cc] - sA8[i * 16 + k] * akc);
        __syncthreads();
        sA8[i * 16 + cc] = nv;
        __syncthreads();
    }

    // W = K b
    for (int idx = tp; idx < PQ; idx += 128) {
        int i = idx / Q_DIM, jj = idx % Q_DIM;
        float w = 0.0f;
        #pragma unroll
        for (int k = 0; k < 8; ++k) w += sA8[i * 16 + 8 + k] * sbias[k * Q_DIM + jj];
        sW8[idx] = w;
    }
    __syncthreads();

    // yb = [[2K - I, -2W], [2W^T, I - 2 b^T W]]
    #pragma unroll
    for (int e = 0; e < 8; ++e) {
        int idx = tp + 128 * e;
        int rr = idx >> 5, cc = idx & 31;
        float y;
        if (rr < 8 && cc < 8) {
            y = 2.0f * sA8[rr * 16 + 8 + cc] - ((rr == cc) ? 1.0f : 0.0f);
        } else if (rr < 8) {
            y = -2.0f * sW8[rr * Q_DIM + (cc - 8)];
        } else if (cc < 8) {
            y = 2.0f * sW8[cc * Q_DIM + (rr - 8)];
        } else {
            int jj = rr - 8, c2 = cc - 8;
            float acc = 0.0f;
            #pragma unroll
            for (int i = 0; i < 8; ++i) acc += sbias[i * Q_DIM + jj] * sW8[i * Q_DIM + c2];
            y = ((jj == c2) ? 1.0f : 0.0f) - 2.0f * acc;
        }
        syb[rr * CPAD + cc] = y;
    }
    __syncthreads();

    // Uq = yb * Q
    #pragma unroll
    for (int k2 = 0; k2 < 2; ++k2) {
        int idx = tp + 128 * k2;
        int rr = idx >> 3, cc = idx & 7;
        float acc = 0.0f;
        #pragma unroll
        for (int k = 0; k < N_DIM; ++k)
            acc += syb[rr * CPAD + k] * sQ[k * RPAD + cc];
        sUq[rr * RPAD + cc] = acc;
    }
    __syncthreads();

    // dist^2 = || Uq Uq^T - Ca Ca^T ||_F^2
    float acc = 0.0f;
    #pragma unroll
    for (int e = 0; e < 8; ++e) {
        int idx = tp + 128 * e;
        int i = idx >> 5, jj = idx & 31;
        const float4* ui = (const float4*)(&sUq[i  * RPAD]);
        const float4* uj = (const float4*)(&sUq[jj * RPAD]);
        const float4* ai = (const float4*)(&sCa[i  * RPAD]);
        const float4* aj = (const float4*)(&sCa[jj * RPAD]);
        float d = 0.0f;
        #pragma unroll
        for (int m = 0; m < 2; ++m) {
            float4 a = ui[m], bq = uj[m], x = ai[m], y = aj[m];
            d += a.x * bq.x + a.y * bq.y + a.z * bq.z + a.w * bq.w;
            d -= x.x * y.x  + x.y * y.y  + x.z * y.z  + x.w * y.w;
        }
        acc += d * d;
    }

    #pragma unroll
    for (int off = 16; off > 0; off >>= 1)
        acc += __shfl_xor_sync(0xFFFFFFFFu, acc, off);
    if ((tp & 31) == 0) red[tp >> 5] = acc;
    __syncthreads();
    if (tp == 0) {
        float s = red[0] + red[1] + red[2] + red[3];
        out[b] = -(*wf) * sqrtf(s) + (*wb);
    }
}

// ---------------------------------------------------------------------------
extern "C" void kernel_launch(void* const* d_in, const int* in_sizes, int n_in,
                              void* d_out, int out_size)
{
    const int*   s1 = (const int*)  d_in[0];   // sentence_1 [512,64]
    const int*   s2 = (const int*)  d_in[1];   // sentence_2 [512,64]
    const float* qe = (const float*)d_in[2];   // question_embedding [32000,8,24]
    const float* ae = (const float*)d_in[3];   // answer_embedding   [32000,8,24]
    const float* qt = (const float*)d_in[4];   // question_transforms [8,24]
    const float* qb = (const float*)d_in[5];   // question_bias [8,24]
    const float* wf = (const float*)d_in[6];
    const float* wb = (const float*)d_in[7];
    float* out = (float*)d_out;

    seq_kernel<<<2 * BATCH, 128>>>(s1, s2, qe, ae, qt, qb, wf, wb, out);
}